// round 3
// baseline (speedup 1.0000x reference)
#include <cuda_runtime.h>

#define NN  100000
#define NE  3200000
#define CIN 128
#define HID 16

// Scratch (no allocations allowed): ~19.6 MB of __device__ globals.
__device__ float g_dinv[NN];          // degree -> dinv (in place)
__device__ float g_feat[NN * HID];    // pre-scaled features fed to edge gather
__device__ float g_agg[NN * HID];     // aggregation target (init = self-loop term)
__device__ float g_h2[NN * HID];      // final embeddings
__device__ int   g_is64;              // 1 if edge_index is int64, 0 if int32

// ---- index dtype detection (runs every launch; deterministic) ----
__global__ void k_detect(const void* ei) {
    __shared__ int bad;
    if (threadIdx.x == 0) bad = 0;
    __syncthreads();
    // sample 256 positions spread across the row-index half
    long long pos = (long long)threadIdx.x * (NE / 256);
    long long v = ((const long long*)ei)[pos];
    if (v < 0 || v >= NN) atomicOr(&bad, 1);
    __syncthreads();
    if (threadIdx.x == 0) g_is64 = bad ? 0 : 1;
}

__device__ __forceinline__ int load_idx(const void* ei, long long pos, int is64) {
    long long v = is64 ? ((const long long*)ei)[pos]
                       : (long long)((const int*)ei)[pos];
    // trap guard: clamp into range (no-op for valid data)
    v = v < 0 ? 0 : (v >= NN ? NN - 1 : v);
    return (int)v;
}

__global__ void k_deg_init() {
    int i = blockIdx.x * blockDim.x + threadIdx.x;
    if (i < NN) g_dinv[i] = 1.0f;   // self-loop contributes 1 to every degree
}

__global__ void k_deg_count(const void* __restrict__ ei) {
    int e = blockIdx.x * blockDim.x + threadIdx.x;
    if (e >= NE) return;
    int is64 = g_is64;
    int c = load_idx(ei, (long long)NE + e, is64);   // col half
    atomicAdd(&g_dinv[c], 1.0f);
}

__global__ void k_rsqrt() {
    int i = blockIdx.x * blockDim.x + threadIdx.x;
    if (i < NN) g_dinv[i] = rsqrtf(g_dinv[i]);   // deg >= 1 always (self-loops)
}

// Layer-1 transform: g = (x @ W1) * dinv ; agg init = g (self-loop term).
// One thread per (node, j). W1 (8 KB) staged in shared.
__global__ void k_xform1(const float* __restrict__ x, const float* __restrict__ W1) {
    __shared__ float sW[CIN * HID];
    for (int t = threadIdx.x; t < CIN * HID; t += blockDim.x) sW[t] = W1[t];
    __syncthreads();
    int tid = blockIdx.x * blockDim.x + threadIdx.x;
    if (tid >= NN * HID) return;
    int node = tid >> 4, j = tid & 15;
    const float4* x4 = (const float4*)(x + (size_t)node * CIN);
    float acc = 0.f;
    #pragma unroll 8
    for (int k4 = 0; k4 < CIN / 4; k4++) {
        float4 xv = x4[k4];
        int k = k4 * 4;
        acc = fmaf(xv.x, sW[(k + 0) * HID + j], acc);
        acc = fmaf(xv.y, sW[(k + 1) * HID + j], acc);
        acc = fmaf(xv.z, sW[(k + 2) * HID + j], acc);
        acc = fmaf(xv.w, sW[(k + 3) * HID + j], acc);
    }
    float v = acc * g_dinv[node];
    g_feat[tid] = v;
    g_agg[tid]  = v;
}

// Edge aggregation: agg[col] += feat[row]. Scalar REDG.ADD.F32 per component.
__global__ void k_edge_agg(const void* __restrict__ ei) {
    int e = blockIdx.x * blockDim.x + threadIdx.x;
    if (e >= NE) return;
    int is64 = g_is64;
    int r = load_idx(ei, e, is64);
    int c = load_idx(ei, (long long)NE + e, is64);
    const float4* src = (const float4*)(g_feat + (size_t)r * HID);
    float* dst = g_agg + (size_t)c * HID;
    #pragma unroll
    for (int q = 0; q < 4; q++) {
        float4 v = src[q];
        atomicAdd(dst + 4*q + 0, v.x);
        atomicAdd(dst + 4*q + 1, v.y);
        atomicAdd(dst + 4*q + 2, v.z);
        atomicAdd(dst + 4*q + 3, v.w);
    }
}

// Layer-2: h1 = relu(dinv*agg1 + b1); g2 = (h1 @ W2) * dinv; agg2 init = g2.
// One thread per node. Reads/writes its own 16-float row, so overwrite is safe.
__global__ void k_layer2(const float* __restrict__ W2, const float* __restrict__ b1) {
    __shared__ float sW[HID * HID];
    __shared__ float sb[HID];
    if (threadIdx.x < HID * HID) sW[threadIdx.x] = W2[threadIdx.x];
    if (threadIdx.x < HID)       sb[threadIdx.x] = b1[threadIdx.x];
    __syncthreads();
    int i = blockIdx.x * blockDim.x + threadIdx.x;
    if (i >= NN) return;
    float dv = g_dinv[i];
    float4* a4 = (float4*)(g_agg + (size_t)i * HID);
    float h[HID];
    #pragma unroll
    for (int q = 0; q < 4; q++) {
        float4 A = a4[q];
        h[4*q + 0] = fmaxf(fmaf(dv, A.x, sb[4*q + 0]), 0.f);
        h[4*q + 1] = fmaxf(fmaf(dv, A.y, sb[4*q + 1]), 0.f);
        h[4*q + 2] = fmaxf(fmaf(dv, A.z, sb[4*q + 2]), 0.f);
        h[4*q + 3] = fmaxf(fmaf(dv, A.w, sb[4*q + 3]), 0.f);
    }
    float ov[HID];
    #pragma unroll
    for (int j = 0; j < HID; j++) {
        float acc = 0.f;
        #pragma unroll
        for (int k = 0; k < HID; k++) acc = fmaf(h[k], sW[k * HID + j], acc);
        ov[j] = acc * dv;
    }
    float4* f4 = (float4*)(g_feat + (size_t)i * HID);
    #pragma unroll
    for (int q = 0; q < 4; q++) {
        float4 w = make_float4(ov[4*q], ov[4*q+1], ov[4*q+2], ov[4*q+3]);
        f4[q] = w;
        a4[q] = w;
    }
}

// Materialize final embeddings: h2 = dinv*agg2 + b2 (elementwise, coalesced).
__global__ void k_h2(const float* __restrict__ b2) {
    int t = blockIdx.x * blockDim.x + threadIdx.x;
    if (t < NN * HID) g_h2[t] = fmaf(g_dinv[t >> 4], g_agg[t], __ldg(&b2[t & 15]));
}

// Per original edge: sigmoid(h2[row] . h2[col]).
__global__ void k_score(const void* __restrict__ ei, float* __restrict__ out) {
    int e = blockIdx.x * blockDim.x + threadIdx.x;
    if (e >= NE) return;
    int is64 = g_is64;
    int r = load_idx(ei, e, is64);
    int c = load_idx(ei, (long long)NE + e, is64);
    const float4* hr = (const float4*)(g_h2 + (size_t)r * HID);
    const float4* hc = (const float4*)(g_h2 + (size_t)c * HID);
    float s = 0.f;
    #pragma unroll
    for (int q = 0; q < 4; q++) {
        float4 a = hr[q], b = hc[q];
        s += a.x * b.x + a.y * b.y + a.z * b.z + a.w * b.w;
    }
    out[e] = 1.0f / (1.0f + __expf(-s));
}

extern "C" void kernel_launch(void* const* d_in, const int* in_sizes, int n_in,
                              void* d_out, int out_size) {
    // Identify inputs by element count — no ordering assumptions.
    const float* x  = nullptr;
    const void*  ei = nullptr;
    const float* W1 = nullptr;
    const float* b1 = nullptr;
    const float* W2 = nullptr;
    const float* b2 = nullptr;
    for (int i = 0; i < n_in; i++) {
        long long n = in_sizes[i];
        if      (n == (long long)NN * CIN)      x  = (const float*)d_in[i];
        else if (n == 2LL * NE)                 ei = d_in[i];
        else if (n == CIN * HID)                W1 = (const float*)d_in[i];
        else if (n == HID * HID)                W2 = (const float*)d_in[i];
        else if (n == HID) { if (!b1) b1 = (const float*)d_in[i]; else b2 = (const float*)d_in[i]; }
    }
    float* out = (float*)d_out;

    const int TB = 256;
    const int gn  = (NN + TB - 1) / TB;
    const int ge  = (NE + TB - 1) / TB;
    const int gnh = (NN * HID + TB - 1) / TB;

    k_detect   <<<1,   256>>>(ei);
    k_deg_init <<<gn,  TB>>>();
    k_deg_count<<<ge,  TB>>>(ei);
    k_rsqrt    <<<gn,  TB>>>();
    k_xform1   <<<gnh, TB>>>(x, W1);
    k_edge_agg <<<ge,  TB>>>(ei);
    k_layer2   <<<gn,  TB>>>(W2, b1);
    k_edge_agg <<<ge,  TB>>>(ei);
    k_h2       <<<gnh, TB>>>(b2);
    k_score    <<<ge,  TB>>>(ei, out);
}

// round 4
// speedup vs baseline: 1.9236x; 1.9236x over previous
#include <cuda_runtime.h>

#define NN  100000
#define NE  3200000
#define CIN 128
#define HID 16

// Scratch (no allocations allowed): ~19.6 MB of __device__ globals.
__device__ float g_dinv[NN];          // degree -> dinv (in place)
__device__ float g_feat[NN * HID];    // pre-scaled features fed to edge gather
__device__ float g_agg[NN * HID];     // aggregation target (init = self-loop term)
__device__ float g_h2[NN * HID];      // final embeddings
__device__ int   g_is64;              // 1 if edge_index is int64, 0 if int32

__device__ __forceinline__ void red_add_v4(float* addr, float4 v) {
    asm volatile("red.global.add.v4.f32 [%0], {%1, %2, %3, %4};"
                 :: "l"(addr), "f"(v.x), "f"(v.y), "f"(v.z), "f"(v.w)
                 : "memory");
}

// ---- index dtype detection (runs every launch; deterministic) ----
__global__ void k_detect(const void* ei) {
    __shared__ int bad;
    if (threadIdx.x == 0) bad = 0;
    __syncthreads();
    long long pos = (long long)threadIdx.x * (NE / 256);
    long long v = ((const long long*)ei)[pos];
    if (v < 0 || v >= NN) atomicOr(&bad, 1);
    __syncthreads();
    if (threadIdx.x == 0) g_is64 = bad ? 0 : 1;
}

__device__ __forceinline__ int load_idx(const void* ei, long long pos, int is64) {
    long long v = is64 ? __ldg((const long long*)ei + pos)
                       : (long long)__ldg((const int*)ei + pos);
    v = v < 0 ? 0 : (v >= NN ? NN - 1 : v);   // trap guard (no-op for valid data)
    return (int)v;
}

__global__ void k_deg_init() {
    int i = blockIdx.x * blockDim.x + threadIdx.x;
    if (i < NN) g_dinv[i] = 1.0f;   // self-loop contributes 1 to every degree
}

__global__ void k_deg_count(const void* __restrict__ ei) {
    int e = blockIdx.x * blockDim.x + threadIdx.x;
    if (e >= NE) return;
    int c = load_idx(ei, (long long)NE + e, g_is64);   // col half
    atomicAdd(&g_dinv[c], 1.0f);
}

__global__ void k_rsqrt() {
    int i = blockIdx.x * blockDim.x + threadIdx.x;
    if (i < NN) g_dinv[i] = rsqrtf(g_dinv[i]);   // deg >= 1 always (self-loops)
}

// Layer-1 transform: g = (x @ W1) * dinv ; agg init = g (self-loop term).
__global__ void k_xform1(const float* __restrict__ x, const float* __restrict__ W1) {
    __shared__ float sW[CIN * HID];
    for (int t = threadIdx.x; t < CIN * HID; t += blockDim.x) sW[t] = W1[t];
    __syncthreads();
    int tid = blockIdx.x * blockDim.x + threadIdx.x;
    if (tid >= NN * HID) return;
    int node = tid >> 4, j = tid & 15;
    const float4* x4 = (const float4*)(x + (size_t)node * CIN);
    float acc = 0.f;
    #pragma unroll 8
    for (int k4 = 0; k4 < CIN / 4; k4++) {
        float4 xv = x4[k4];
        int k = k4 * 4;
        acc = fmaf(xv.x, sW[(k + 0) * HID + j], acc);
        acc = fmaf(xv.y, sW[(k + 1) * HID + j], acc);
        acc = fmaf(xv.z, sW[(k + 2) * HID + j], acc);
        acc = fmaf(xv.w, sW[(k + 3) * HID + j], acc);
    }
    float v = acc * g_dinv[node];
    g_feat[tid] = v;
    g_agg[tid]  = v;
}

// Edge aggregation: agg[col] += feat[row]. 4x red.global.add.v4.f32 per edge.
__global__ void k_edge_agg(const void* __restrict__ ei) {
    int e = blockIdx.x * blockDim.x + threadIdx.x;
    if (e >= NE) return;
    int is64 = g_is64;
    int r = load_idx(ei, e, is64);
    int c = load_idx(ei, (long long)NE + e, is64);
    const float4* src = (const float4*)(g_feat + (size_t)r * HID);
    float4 v0 = src[0], v1 = src[1], v2 = src[2], v3 = src[3];
    float* dst = g_agg + (size_t)c * HID;
    red_add_v4(dst + 0,  v0);
    red_add_v4(dst + 4,  v1);
    red_add_v4(dst + 8,  v2);
    red_add_v4(dst + 12, v3);
}

// Layer-2: h1 = relu(dinv*agg1 + b1); g2 = (h1 @ W2) * dinv; agg2 init = g2.
__global__ void k_layer2(const float* __restrict__ W2, const float* __restrict__ b1) {
    __shared__ float sW[HID * HID];
    __shared__ float sb[HID];
    if (threadIdx.x < HID * HID) sW[threadIdx.x] = W2[threadIdx.x];
    if (threadIdx.x < HID)       sb[threadIdx.x] = b1[threadIdx.x];
    __syncthreads();
    int i = blockIdx.x * blockDim.x + threadIdx.x;
    if (i >= NN) return;
    float dv = g_dinv[i];
    float4* a4 = (float4*)(g_agg + (size_t)i * HID);
    float h[HID];
    #pragma unroll
    for (int q = 0; q < 4; q++) {
        float4 A = a4[q];
        h[4*q + 0] = fmaxf(fmaf(dv, A.x, sb[4*q + 0]), 0.f);
        h[4*q + 1] = fmaxf(fmaf(dv, A.y, sb[4*q + 1]), 0.f);
        h[4*q + 2] = fmaxf(fmaf(dv, A.z, sb[4*q + 2]), 0.f);
        h[4*q + 3] = fmaxf(fmaf(dv, A.w, sb[4*q + 3]), 0.f);
    }
    float ov[HID];
    #pragma unroll
    for (int j = 0; j < HID; j++) {
        float acc = 0.f;
        #pragma unroll
        for (int k = 0; k < HID; k++) acc = fmaf(h[k], sW[k * HID + j], acc);
        ov[j] = acc * dv;
    }
    float4* f4 = (float4*)(g_feat + (size_t)i * HID);
    #pragma unroll
    for (int q = 0; q < 4; q++) {
        float4 w = make_float4(ov[4*q], ov[4*q+1], ov[4*q+2], ov[4*q+3]);
        f4[q] = w;
        a4[q] = w;
    }
}

// Materialize final embeddings: h2 = dinv*agg2 + b2 (elementwise, coalesced).
__global__ void k_h2(const float* __restrict__ b2) {
    int t = blockIdx.x * blockDim.x + threadIdx.x;
    if (t < NN * HID) g_h2[t] = fmaf(g_dinv[t >> 4], g_agg[t], __ldg(&b2[t & 15]));
}

// Per original edge: sigmoid(h2[row] . h2[col]).
__global__ void k_score(const void* __restrict__ ei, float* __restrict__ out) {
    int e = blockIdx.x * blockDim.x + threadIdx.x;
    if (e >= NE) return;
    int is64 = g_is64;
    int r = load_idx(ei, e, is64);
    int c = load_idx(ei, (long long)NE + e, is64);
    const float4* hr = (const float4*)(g_h2 + (size_t)r * HID);
    const float4* hc = (const float4*)(g_h2 + (size_t)c * HID);
    float s = 0.f;
    #pragma unroll
    for (int q = 0; q < 4; q++) {
        float4 a = hr[q], b = hc[q];
        s += a.x * b.x + a.y * b.y + a.z * b.z + a.w * b.w;
    }
    out[e] = 1.0f / (1.0f + __expf(-s));
}

extern "C" void kernel_launch(void* const* d_in, const int* in_sizes, int n_in,
                              void* d_out, int out_size) {
    // Identify inputs by element count — no ordering assumptions.
    const float* x  = nullptr;
    const void*  ei = nullptr;
    const float* W1 = nullptr;
    const float* b1 = nullptr;
    const float* W2 = nullptr;
    const float* b2 = nullptr;
    for (int i = 0; i < n_in; i++) {
        long long n = in_sizes[i];
        if      (n == (long long)NN * CIN)      x  = (const float*)d_in[i];
        else if (n == 2LL * NE)                 ei = d_in[i];
        else if (n == CIN * HID)                W1 = (const float*)d_in[i];
        else if (n == HID * HID)                W2 = (const float*)d_in[i];
        else if (n == HID) { if (!b1) b1 = (const float*)d_in[i]; else b2 = (const float*)d_in[i]; }
    }
    float* out = (float*)d_out;

    const int TB  = 256;
    const int TBE = 512;
    const int gn  = (NN + TB - 1) / TB;
    const int ge  = (NE + TBE - 1) / TBE;
    const int gnh = (NN * HID + TB - 1) / TB;

    k_detect   <<<1,   256>>>(ei);
    k_deg_init <<<gn,  TB>>>();
    k_deg_count<<<ge,  TBE>>>(ei);
    k_rsqrt    <<<gn,  TB>>>();
    k_xform1   <<<gnh, TB>>>(x, W1);
    k_edge_agg <<<ge,  TBE>>>(ei);
    k_layer2   <<<gn,  TB>>>(W2, b1);
    k_edge_agg <<<ge,  TBE>>>(ei);
    k_h2       <<<gnh, TB>>>(b2);
    k_score    <<<ge,  TBE>>>(ei, out);
}

// round 5
// speedup vs baseline: 1.9267x; 1.0016x over previous
#include <cuda_runtime.h>

#define NN  100000
#define NE  3200000
#define CIN 128
#define HID 16

// Scratch (no allocations allowed): ~20 MB of __device__ globals.
__device__ float g_deg[NN];           // degree
__device__ float g_dinv[NN];          // rsqrt(degree)
__device__ float g_feat[NN * HID];    // pre-scaled features fed to edge gather
__device__ float g_agg[NN * HID];     // aggregation target (init = self-loop term)
__device__ float g_h2[NN * HID];      // final embeddings
__device__ int   g_is64;              // 1 if edge_index is int64, 0 if int32

__device__ __forceinline__ void red_add_v4(float* addr, float4 v) {
    asm volatile("red.global.add.v4.f32 [%0], {%1, %2, %3, %4};"
                 :: "l"(addr), "f"(v.x), "f"(v.y), "f"(v.z), "f"(v.w)
                 : "memory");
}

// ---- index dtype detection (runs every launch; deterministic) ----
__global__ void k_detect(const void* ei) {
    __shared__ int bad;
    if (threadIdx.x == 0) bad = 0;
    __syncthreads();
    long long pos = (long long)threadIdx.x * (NE / 256);
    long long v = ((const long long*)ei)[pos];
    if (v < 0 || v >= NN) atomicOr(&bad, 1);
    __syncthreads();
    if (threadIdx.x == 0) g_is64 = bad ? 0 : 1;
}

__device__ __forceinline__ int clampi(long long v) {
    v = v < 0 ? 0 : (v >= NN ? NN - 1 : v);
    return (int)v;
}

// Load 4 consecutive indices starting at element pos (pos % 4 == 0).
__device__ __forceinline__ int4 load_idx4(const void* ei, long long pos, int is64) {
    if (!is64) {
        int4 t = __ldg((const int4*)((const int*)ei + pos));
        return make_int4(clampi(t.x), clampi(t.y), clampi(t.z), clampi(t.w));
    } else {
        longlong2 a = __ldg((const longlong2*)((const long long*)ei + pos));
        longlong2 b = __ldg((const longlong2*)((const long long*)ei + pos + 2));
        return make_int4(clampi(a.x), clampi(a.y), clampi(b.x), clampi(b.y));
    }
}

__global__ void k_deg_init() {
    int i = blockIdx.x * blockDim.x + threadIdx.x;
    if (i < NN) g_deg[i] = 1.0f;   // self-loop contributes 1 to every degree
}

__global__ void k_deg_count(const void* __restrict__ ei) {
    int t = blockIdx.x * blockDim.x + threadIdx.x;
    long long e = (long long)t * 4;
    if (e >= NE) return;
    int4 c = load_idx4(ei, (long long)NE + e, g_is64);   // col half
    atomicAdd(&g_deg[c.x], 1.0f);
    atomicAdd(&g_deg[c.y], 1.0f);
    atomicAdd(&g_deg[c.z], 1.0f);
    atomicAdd(&g_deg[c.w], 1.0f);
}

// Layer-1 transform: dinv = rsqrt(deg); g = (x @ W1) * dinv ; agg init = g.
__global__ void k_xform1(const float* __restrict__ x, const float* __restrict__ W1) {
    __shared__ float sW[CIN * HID];
    for (int t = threadIdx.x; t < CIN * HID; t += blockDim.x) sW[t] = W1[t];
    __syncthreads();
    int tid = blockIdx.x * blockDim.x + threadIdx.x;
    if (tid >= NN * HID) return;
    int node = tid >> 4, j = tid & 15;
    float dv = rsqrtf(g_deg[node]);     // deg >= 1 always (self-loops)
    if (j == 0) g_dinv[node] = dv;
    const float4* x4 = (const float4*)(x + (size_t)node * CIN);
    float acc = 0.f;
    #pragma unroll 8
    for (int k4 = 0; k4 < CIN / 4; k4++) {
        float4 xv = x4[k4];
        int k = k4 * 4;
        acc = fmaf(xv.x, sW[(k + 0) * HID + j], acc);
        acc = fmaf(xv.y, sW[(k + 1) * HID + j], acc);
        acc = fmaf(xv.z, sW[(k + 2) * HID + j], acc);
        acc = fmaf(xv.w, sW[(k + 3) * HID + j], acc);
    }
    float v = acc * dv;
    g_feat[tid] = v;
    g_agg[tid]  = v;
}

// Edge aggregation: agg[col] += feat[row]. 4 edges/thread, v4 REDs.
__global__ void k_edge_agg(const void* __restrict__ ei) {
    int t = blockIdx.x * blockDim.x + threadIdx.x;
    long long e = (long long)t * 4;
    if (e >= NE) return;
    int is64 = g_is64;
    int4 r4 = load_idx4(ei, e, is64);
    int4 c4 = load_idx4(ei, (long long)NE + e, is64);
    int rr[4] = {r4.x, r4.y, r4.z, r4.w};
    int cc[4] = {c4.x, c4.y, c4.z, c4.w};
    #pragma unroll
    for (int k = 0; k < 4; k++) {
        const float4* src = (const float4*)(g_feat + (size_t)rr[k] * HID);
        float4 v0 = src[0], v1 = src[1], v2 = src[2], v3 = src[3];
        float* dst = g_agg + (size_t)cc[k] * HID;
        red_add_v4(dst + 0,  v0);
        red_add_v4(dst + 4,  v1);
        red_add_v4(dst + 8,  v2);
        red_add_v4(dst + 12, v3);
    }
}

// Layer-2: h1 = relu(dinv*agg1 + b1); g2 = (h1 @ W2) * dinv; agg2 init = g2.
__global__ void k_layer2(const float* __restrict__ W2, const float* __restrict__ b1) {
    __shared__ float sW[HID * HID];
    __shared__ float sb[HID];
    if (threadIdx.x < HID * HID) sW[threadIdx.x] = W2[threadIdx.x];
    if (threadIdx.x < HID)       sb[threadIdx.x] = b1[threadIdx.x];
    __syncthreads();
    int i = blockIdx.x * blockDim.x + threadIdx.x;
    if (i >= NN) return;
    float dv = g_dinv[i];
    float4* a4 = (float4*)(g_agg + (size_t)i * HID);
    float h[HID];
    #pragma unroll
    for (int q = 0; q < 4; q++) {
        float4 A = a4[q];
        h[4*q + 0] = fmaxf(fmaf(dv, A.x, sb[4*q + 0]), 0.f);
        h[4*q + 1] = fmaxf(fmaf(dv, A.y, sb[4*q + 1]), 0.f);
        h[4*q + 2] = fmaxf(fmaf(dv, A.z, sb[4*q + 2]), 0.f);
        h[4*q + 3] = fmaxf(fmaf(dv, A.w, sb[4*q + 3]), 0.f);
    }
    float ov[HID];
    #pragma unroll
    for (int j = 0; j < HID; j++) {
        float acc = 0.f;
        #pragma unroll
        for (int k = 0; k < HID; k++) acc = fmaf(h[k], sW[k * HID + j], acc);
        ov[j] = acc * dv;
    }
    float4* f4 = (float4*)(g_feat + (size_t)i * HID);
    #pragma unroll
    for (int q = 0; q < 4; q++) {
        float4 w = make_float4(ov[4*q], ov[4*q+1], ov[4*q+2], ov[4*q+3]);
        f4[q] = w;
        a4[q] = w;
    }
}

// Materialize final embeddings: h2 = dinv*agg2 + b2 (elementwise, coalesced).
__global__ void k_h2(const float* __restrict__ b2) {
    int t = blockIdx.x * blockDim.x + threadIdx.x;
    if (t < NN * HID) g_h2[t] = fmaf(g_dinv[t >> 4], g_agg[t], __ldg(&b2[t & 15]));
}

// Per original edge: sigmoid(h2[row] . h2[col]). 4 edges/thread, float4 out.
__global__ void k_score(const void* __restrict__ ei, float* __restrict__ out) {
    int t = blockIdx.x * blockDim.x + threadIdx.x;
    long long e = (long long)t * 4;
    if (e >= NE) return;
    int is64 = g_is64;
    int4 r4 = load_idx4(ei, e, is64);
    int4 c4 = load_idx4(ei, (long long)NE + e, is64);
    int rr[4] = {r4.x, r4.y, r4.z, r4.w};
    int cc[4] = {c4.x, c4.y, c4.z, c4.w};
    float s[4];
    #pragma unroll
    for (int k = 0; k < 4; k++) {
        const float4* hr = (const float4*)(g_h2 + (size_t)rr[k] * HID);
        const float4* hc = (const float4*)(g_h2 + (size_t)cc[k] * HID);
        float acc = 0.f;
        #pragma unroll
        for (int q = 0; q < 4; q++) {
            float4 a = hr[q], b = hc[q];
            acc += a.x * b.x + a.y * b.y + a.z * b.z + a.w * b.w;
        }
        s[k] = 1.0f / (1.0f + __expf(-acc));
    }
    *((float4*)(out + e)) = make_float4(s[0], s[1], s[2], s[3]);
}

extern "C" void kernel_launch(void* const* d_in, const int* in_sizes, int n_in,
                              void* d_out, int out_size) {
    // Identify inputs by element count — no ordering assumptions.
    const float* x  = nullptr;
    const void*  ei = nullptr;
    const float* W1 = nullptr;
    const float* b1 = nullptr;
    const float* W2 = nullptr;
    const float* b2 = nullptr;
    for (int i = 0; i < n_in; i++) {
        long long n = in_sizes[i];
        if      (n == (long long)NN * CIN)      x  = (const float*)d_in[i];
        else if (n == 2LL * NE)                 ei = d_in[i];
        else if (n == CIN * HID)                W1 = (const float*)d_in[i];
        else if (n == HID * HID)                W2 = (const float*)d_in[i];
        else if (n == HID) { if (!b1) b1 = (const float*)d_in[i]; else b2 = (const float*)d_in[i]; }
    }
    float* out = (float*)d_out;

    const int TB  = 256;
    const int gn  = (NN + TB - 1) / TB;
    const int ge4 = (NE / 4 + TB - 1) / TB;
    const int gnh = (NN * HID + TB - 1) / TB;

    k_detect   <<<1,   256>>>(ei);
    k_deg_init <<<gn,  TB>>>();
    k_deg_count<<<ge4, TB>>>(ei);
    k_xform1   <<<gnh, TB>>>(x, W1);
    k_edge_agg <<<ge4, TB>>>(ei);
    k_layer2   <<<gn,  TB>>>(W2, b1);
    k_edge_agg <<<ge4, TB>>>(ei);
    k_h2       <<<gnh, TB>>>(b2);
    k_score    <<<ge4, TB>>>(ei, out);
}

// round 7
// speedup vs baseline: 1.9749x; 1.0250x over previous
#include <cuda_runtime.h>

#define NN  100000
#define NE  3200000
#define CIN 128
#define HID 16

// Scratch (no allocations allowed): ~20 MB of __device__ globals.
__device__ float g_deg[NN];           // degree
__device__ float g_dinv[NN];          // rsqrt(degree)
__device__ float g_feat[NN * HID];    // pre-scaled features fed to edge gather
__device__ float g_agg[NN * HID];     // aggregation target (init = self-loop term)
__device__ float g_h2[NN * HID];      // final embeddings
__device__ int   g_is64;              // 1 if edge_index is int64, 0 if int32

__device__ __forceinline__ void red_add_v4(float* addr, float4 v) {
    asm volatile("red.global.add.v4.f32 [%0], {%1, %2, %3, %4};"
                 :: "l"(addr), "f"(v.x), "f"(v.y), "f"(v.z), "f"(v.w)
                 : "memory");
}

__device__ __forceinline__ int clampi(long long v) {
    v = v < 0 ? 0 : (v >= NN ? NN - 1 : v);
    return (int)v;
}

// Load 4 consecutive indices starting at element pos (pos % 4 == 0).
__device__ __forceinline__ int4 load_idx4(const void* ei, long long pos, int is64) {
    if (!is64) {
        int4 t = __ldg((const int4*)((const int*)ei + pos));
        return make_int4(clampi(t.x), clampi(t.y), clampi(t.z), clampi(t.w));
    } else {
        longlong2 a = __ldg((const longlong2*)((const long long*)ei + pos));
        longlong2 b = __ldg((const longlong2*)((const long long*)ei + pos + 2));
        return make_int4(clampi(a.x), clampi(a.y), clampi(b.x), clampi(b.y));
    }
}

// deg init + (block 0) index-dtype detection, fused.
__global__ void k_deg_init(const void* ei) {
    if (blockIdx.x == 0) {
        __shared__ int bad;
        if (threadIdx.x == 0) bad = 0;
        __syncthreads();
        long long pos = (long long)threadIdx.x * (NE / 256);
        long long v = ((const long long*)ei)[pos];
        if (v < 0 || v >= NN) atomicOr(&bad, 1);
        __syncthreads();
        if (threadIdx.x == 0) g_is64 = bad ? 0 : 1;
    }
    int i = blockIdx.x * blockDim.x + threadIdx.x;
    if (i < NN) g_deg[i] = 1.0f;   // self-loop contributes 1 to every degree
}

__global__ void k_deg_count(const void* __restrict__ ei) {
    int t = blockIdx.x * blockDim.x + threadIdx.x;
    long long e = (long long)t * 4;
    if (e >= NE) return;
    int4 c = load_idx4(ei, (long long)NE + e, g_is64);   // col half
    atomicAdd(&g_deg[c.x], 1.0f);
    atomicAdd(&g_deg[c.y], 1.0f);
    atomicAdd(&g_deg[c.z], 1.0f);
    atomicAdd(&g_deg[c.w], 1.0f);
}

// Layer-1 transform with shared staging: 16 nodes/block.
// dinv = rsqrt(deg); g = (x @ W1) * dinv ; agg init = g (self-loop term).
#define XS_STR 132   // padded row stride (floats) — kills bank conflicts, keeps 16B align
__global__ void k_xform1(const float* __restrict__ x, const float* __restrict__ W1) {
    __shared__ float sX[16 * XS_STR];    // x tile, padded
    __shared__ float sWt[HID * XS_STR];  // W1 transposed [j][k], padded

    // Stage x tile (coalesced global reads, scattered padded smem writes)
    const float* xb = x + (size_t)blockIdx.x * 16 * CIN;
    #pragma unroll
    for (int L = threadIdx.x; L < 16 * CIN; L += 256) {
        int n = L >> 7, k = L & 127;
        sX[n * XS_STR + k] = xb[L];
    }
    // Stage W1 transposed
    #pragma unroll
    for (int L = threadIdx.x; L < CIN * HID; L += 256) {
        int k = L >> 4, j = L & 15;
        sWt[j * XS_STR + k] = W1[L];
    }
    __syncthreads();

    int nloc = threadIdx.x >> 4;          // 0..15
    int j    = threadIdx.x & 15;
    int node = blockIdx.x * 16 + nloc;
    const float4* xr = (const float4*)(sX  + nloc * XS_STR);
    const float4* wr = (const float4*)(sWt + j    * XS_STR);
    float acc = 0.f;
    #pragma unroll
    for (int k4 = 0; k4 < CIN / 4; k4++) {
        float4 xv = xr[k4];
        float4 wv = wr[k4];
        acc = fmaf(xv.x, wv.x, acc);
        acc = fmaf(xv.y, wv.y, acc);
        acc = fmaf(xv.z, wv.z, acc);
        acc = fmaf(xv.w, wv.w, acc);
    }
    float dv = rsqrtf(g_deg[node]);       // deg >= 1 always
    if (j == 0) g_dinv[node] = dv;
    float v = acc * dv;
    int tid = blockIdx.x * 256 + threadIdx.x;   // == node*16 + j
    g_feat[tid] = v;
    g_agg[tid]  = v;
}

// Edge aggregation: agg[col] += feat[row]. 4 edges/thread, v4 REDs.
__global__ void k_edge_agg(const void* __restrict__ ei) {
    int t = blockIdx.x * blockDim.x + threadIdx.x;
    long long e = (long long)t * 4;
    if (e >= NE) return;
    int is64 = g_is64;
    int4 r4 = load_idx4(ei, e, is64);
    int4 c4 = load_idx4(ei, (long long)NE + e, is64);
    int rr[4] = {r4.x, r4.y, r4.z, r4.w};
    int cc[4] = {c4.x, c4.y, c4.z, c4.w};
    #pragma unroll
    for (int k = 0; k < 4; k++) {
        const float4* src = (const float4*)(g_feat + (size_t)rr[k] * HID);
        float4 v0 = src[0], v1 = src[1], v2 = src[2], v3 = src[3];
        float* dst = g_agg + (size_t)cc[k] * HID;
        red_add_v4(dst + 0,  v0);
        red_add_v4(dst + 4,  v1);
        red_add_v4(dst + 8,  v2);
        red_add_v4(dst + 12, v3);
    }
}

// Layer-2: h1 = relu(dinv*agg1 + b1); g2 = (h1 @ W2) * dinv; agg2 init = g2.
__global__ void k_layer2(const float* __restrict__ W2, const float* __restrict__ b1) {
    __shared__ float sW[HID * HID];
    __shared__ float sb[HID];
    if (threadIdx.x < HID * HID) sW[threadIdx.x] = W2[threadIdx.x];
    if (threadIdx.x < HID)       sb[threadIdx.x] = b1[threadIdx.x];
    __syncthreads();
    int i = blockIdx.x * blockDim.x + threadIdx.x;
    if (i >= NN) return;
    float dv = g_dinv[i];
    float4* a4 = (float4*)(g_agg + (size_t)i * HID);
    float h[HID];
    #pragma unroll
    for (int q = 0; q < 4; q++) {
        float4 A = a4[q];
        h[4*q + 0] = fmaxf(fmaf(dv, A.x, sb[4*q + 0]), 0.f);
        h[4*q + 1] = fmaxf(fmaf(dv, A.y, sb[4*q + 1]), 0.f);
        h[4*q + 2] = fmaxf(fmaf(dv, A.z, sb[4*q + 2]), 0.f);
        h[4*q + 3] = fmaxf(fmaf(dv, A.w, sb[4*q + 3]), 0.f);
    }
    float ov[HID];
    #pragma unroll
    for (int j = 0; j < HID; j++) {
        float acc = 0.f;
        #pragma unroll
        for (int k = 0; k < HID; k++) acc = fmaf(h[k], sW[k * HID + j], acc);
        ov[j] = acc * dv;
    }
    float4* f4 = (float4*)(g_feat + (size_t)i * HID);
    #pragma unroll
    for (int q = 0; q < 4; q++) {
        float4 w = make_float4(ov[4*q], ov[4*q+1], ov[4*q+2], ov[4*q+3]);
        f4[q] = w;
        a4[q] = w;
    }
}

// Materialize final embeddings: h2 = dinv*agg2 + b2 (elementwise, coalesced).
__global__ void k_h2(const float* __restrict__ b2) {
    int t = blockIdx.x * blockDim.x + threadIdx.x;
    if (t < NN * HID) g_h2[t] = fmaf(g_dinv[t >> 4], g_agg[t], __ldg(&b2[t & 15]));
}

// Per original edge: sigmoid(h2[row] . h2[col]). 4 edges/thread, float4 out.
__global__ void k_score(const void* __restrict__ ei, float* __restrict__ out) {
    int t = blockIdx.x * blockDim.x + threadIdx.x;
    long long e = (long long)t * 4;
    if (e >= NE) return;
    int is64 = g_is64;
    int4 r4 = load_idx4(ei, e, is64);
    int4 c4 = load_idx4(ei, (long long)NE + e, is64);
    int rr[4] = {r4.x, r4.y, r4.z, r4.w};
    int cc[4] = {c4.x, c4.y, c4.z, c4.w};
    float s[4];
    #pragma unroll
    for (int k = 0; k < 4; k++) {
        const float4* hr = (const float4*)(g_h2 + (size_t)rr[k] * HID);
        const float4* hc = (const float4*)(g_h2 + (size_t)cc[k] * HID);
        float acc = 0.f;
        #pragma unroll
        for (int q = 0; q < 4; q++) {
            float4 a = hr[q], b = hc[q];
            acc += a.x * b.x + a.y * b.y + a.z * b.z + a.w * b.w;
        }
        s[k] = 1.0f / (1.0f + __expf(-acc));
    }
    *((float4*)(out + e)) = make_float4(s[0], s[1], s[2], s[3]);
}

extern "C" void kernel_launch(void* const* d_in, const int* in_sizes, int n_in,
                              void* d_out, int out_size) {
    // Identify inputs by element count — no ordering assumptions.
    const float* x  = nullptr;
    const void*  ei = nullptr;
    const float* W1 = nullptr;
    const float* b1 = nullptr;
    const float* W2 = nullptr;
    const float* b2 = nullptr;
    for (int i = 0; i < n_in; i++) {
        long long n = in_sizes[i];
        if      (n == (long long)NN * CIN)      x  = (const float*)d_in[i];
        else if (n == 2LL * NE)                 ei = d_in[i];
        else if (n == CIN * HID)                W1 = (const float*)d_in[i];
        else if (n == HID * HID)                W2 = (const float*)d_in[i];
        else if (n == HID) { if (!b1) b1 = (const float*)d_in[i]; else b2 = (const float*)d_in[i]; }
    }
    float* out = (float*)d_out;

    const int TB  = 256;
    const int gn  = (NN + TB - 1) / TB;
    const int ge4 = (NE / 4 + TB - 1) / TB;

    k_deg_init <<<gn,   TB>>>(ei);        // #1 (includes dtype detect in block 0)
    k_deg_count<<<ge4,  TB>>>(ei);        // #2
    k_xform1   <<<NN/16, TB>>>(x, W1);    // #3
    k_edge_agg <<<ge4,  TB>>>(ei);        // #4  <- profiler slot
    k_layer2   <<<gn,   TB>>>(W2, b1);    // #5
    k_edge_agg <<<ge4,  TB>>>(ei);        // #6
    k_h2       <<<gn * HID, TB>>>(b2);    // #7
    k_score    <<<ge4,  TB>>>(ei, out);   // #8
}

// round 8
// speedup vs baseline: 2.2676x; 1.1482x over previous
#include <cuda_runtime.h>

#define NN  100000
#define NE  3200000
#define CIN 128
#define HID 16

// Scratch (no allocations allowed): ~33 MB of __device__ globals.
__device__ int   g_degi[NN];          // in-degree (excl. self)
__device__ float g_dinv[NN];          // rsqrt(1+deg)
__device__ int   g_off[NN];           // CSR segment start
__device__ int   g_cur[NN];           // fill cursor
__device__ int   g_nbr[NE];           // CSR: source node per incoming edge
__device__ int   g_total;             // segment allocator
__device__ float g_feat[NN * HID];    // pre-scaled features fed to edge gather
__device__ float g_agg[NN * HID];     // aggregation target (init = self-loop term)
__device__ float g_h2[NN * HID];      // final embeddings
__device__ int   g_is64;              // 1 if edge_index is int64, 0 if int32

__device__ __forceinline__ int clampi(long long v) {
    v = v < 0 ? 0 : (v >= NN ? NN - 1 : v);
    return (int)v;
}

// Load 4 consecutive indices starting at element pos (pos % 4 == 0).
__device__ __forceinline__ int4 load_idx4(const void* ei, long long pos, int is64) {
    if (!is64) {
        int4 t = __ldg((const int4*)((const int*)ei + pos));
        return make_int4(clampi(t.x), clampi(t.y), clampi(t.z), clampi(t.w));
    } else {
        longlong2 a = __ldg((const longlong2*)((const long long*)ei + pos));
        longlong2 b = __ldg((const longlong2*)((const long long*)ei + pos + 2));
        return make_int4(clampi(a.x), clampi(a.y), clampi(b.x), clampi(b.y));
    }
}

// zero counters + (block 0) index-dtype detection, fused.
__global__ void k_deg_init(const void* ei) {
    if (blockIdx.x == 0) {
        __shared__ int bad;
        if (threadIdx.x == 0) { bad = 0; g_total = 0; }
        __syncthreads();
        long long pos = (long long)threadIdx.x * (NE / 256);
        long long v = ((const long long*)ei)[pos];
        if (v < 0 || v >= NN) atomicOr(&bad, 1);
        __syncthreads();
        if (threadIdx.x == 0) g_is64 = bad ? 0 : 1;
    }
    int i = blockIdx.x * blockDim.x + threadIdx.x;
    if (i < NN) g_degi[i] = 0;
}

__global__ void k_deg_count(const void* __restrict__ ei) {
    int t = blockIdx.x * blockDim.x + threadIdx.x;
    long long e = (long long)t * 4;
    if (e >= NE) return;
    int4 c = load_idx4(ei, (long long)NE + e, g_is64);   // col half
    atomicAdd(&g_degi[c.x], 1);
    atomicAdd(&g_degi[c.y], 1);
    atomicAdd(&g_degi[c.z], 1);
    atomicAdd(&g_degi[c.w], 1);
}

// Per-block exclusive scan + global segment allocation; also dinv = rsqrt(1+deg).
__global__ void k_offsets() {
    __shared__ int s[256];
    __shared__ int base;
    int i = blockIdx.x * 256 + threadIdx.x;
    int d = (i < NN) ? g_degi[i] : 0;
    s[threadIdx.x] = d;
    __syncthreads();
    #pragma unroll
    for (int ofs = 1; ofs < 256; ofs <<= 1) {
        int v = (threadIdx.x >= ofs) ? s[threadIdx.x - ofs] : 0;
        __syncthreads();
        s[threadIdx.x] += v;
        __syncthreads();
    }
    if (threadIdx.x == 255) base = atomicAdd(&g_total, s[255]);
    __syncthreads();
    if (i < NN) {
        int excl = base + s[threadIdx.x] - d;
        g_off[i] = excl;
        g_cur[i] = excl;
        g_dinv[i] = rsqrtf(1.0f + (float)d);
    }
}

// CSR fill: nbr[cursor[col]++] = row. Order within a segment is arbitrary.
__global__ void k_fill(const void* __restrict__ ei) {
    int t = blockIdx.x * blockDim.x + threadIdx.x;
    long long e = (long long)t * 4;
    if (e >= NE) return;
    int is64 = g_is64;
    int4 r4 = load_idx4(ei, e, is64);
    int4 c4 = load_idx4(ei, (long long)NE + e, is64);
    int rr[4] = {r4.x, r4.y, r4.z, r4.w};
    int cc[4] = {c4.x, c4.y, c4.z, c4.w};
    #pragma unroll
    for (int k = 0; k < 4; k++) {
        int pos = atomicAdd(&g_cur[cc[k]], 1);
        g_nbr[pos] = rr[k];
    }
}

// Layer-1 transform with shared staging: 16 nodes/block.
// g = (x @ W1) * dinv ; agg init = g (self-loop term).
#define XS_STR 132   // padded row stride (floats)
__global__ void k_xform1(const float* __restrict__ x, const float* __restrict__ W1) {
    __shared__ float sX[16 * XS_STR];
    __shared__ float sWt[HID * XS_STR];
    const float* xb = x + (size_t)blockIdx.x * 16 * CIN;
    #pragma unroll
    for (int L = threadIdx.x; L < 16 * CIN; L += 256) {
        int n = L >> 7, k = L & 127;
        sX[n * XS_STR + k] = xb[L];
    }
    #pragma unroll
    for (int L = threadIdx.x; L < CIN * HID; L += 256) {
        int k = L >> 4, j = L & 15;
        sWt[j * XS_STR + k] = W1[L];
    }
    __syncthreads();
    int nloc = threadIdx.x >> 4;
    int j    = threadIdx.x & 15;
    int node = blockIdx.x * 16 + nloc;
    const float4* xr = (const float4*)(sX  + nloc * XS_STR);
    const float4* wr = (const float4*)(sWt + j    * XS_STR);
    float acc = 0.f;
    #pragma unroll
    for (int k4 = 0; k4 < CIN / 4; k4++) {
        float4 xv = xr[k4];
        float4 wv = wr[k4];
        acc = fmaf(xv.x, wv.x, acc);
        acc = fmaf(xv.y, wv.y, acc);
        acc = fmaf(xv.z, wv.z, acc);
        acc = fmaf(xv.w, wv.w, acc);
    }
    float v = acc * g_dinv[node];
    int tid = blockIdx.x * 256 + threadIdx.x;
    g_feat[tid] = v;
    g_agg[tid]  = v;
}

// Pull aggregation: one warp per node; agg[c] += sum over incoming feat rows.
__global__ void k_pull() {
    int warp = (blockIdx.x * blockDim.x + threadIdx.x) >> 5;
    if (warp >= NN) return;
    int lane = threadIdx.x & 31;
    int j    = lane & 15;
    int half = lane >> 4;             // 0 or 1
    int start = g_off[warp];
    int deg   = g_degi[warp];
    float acc = 0.f;
    for (int base = 0; base < deg; base += 32) {
        int myn = (base + lane < deg) ? g_nbr[start + base + lane] : 0;
        int lim = min(32, deg - base);
        #pragma unroll 4
        for (int k = 0; k < 32; k += 2) {
            if (k >= lim) break;
            int r = __shfl_sync(0xffffffffu, myn, k + half);
            if (k + half < lim)
                acc += g_feat[(size_t)r * HID + j];
        }
    }
    acc += __shfl_xor_sync(0xffffffffu, acc, 16);
    if (lane < 16) g_agg[(size_t)warp * HID + j] += acc;
}

// Layer-2: h1 = relu(dinv*agg1 + b1); g2 = (h1 @ W2) * dinv; agg2 init = g2.
__global__ void k_layer2(const float* __restrict__ W2, const float* __restrict__ b1) {
    __shared__ float sW[HID * HID];
    __shared__ float sb[HID];
    if (threadIdx.x < HID * HID) sW[threadIdx.x] = W2[threadIdx.x];
    if (threadIdx.x < HID)       sb[threadIdx.x] = b1[threadIdx.x];
    __syncthreads();
    int i = blockIdx.x * blockDim.x + threadIdx.x;
    if (i >= NN) return;
    float dv = g_dinv[i];
    float4* a4 = (float4*)(g_agg + (size_t)i * HID);
    float h[HID];
    #pragma unroll
    for (int q = 0; q < 4; q++) {
        float4 A = a4[q];
        h[4*q + 0] = fmaxf(fmaf(dv, A.x, sb[4*q + 0]), 0.f);
        h[4*q + 1] = fmaxf(fmaf(dv, A.y, sb[4*q + 1]), 0.f);
        h[4*q + 2] = fmaxf(fmaf(dv, A.z, sb[4*q + 2]), 0.f);
        h[4*q + 3] = fmaxf(fmaf(dv, A.w, sb[4*q + 3]), 0.f);
    }
    float ov[HID];
    #pragma unroll
    for (int j = 0; j < HID; j++) {
        float acc = 0.f;
        #pragma unroll
        for (int k = 0; k < HID; k++) acc = fmaf(h[k], sW[k * HID + j], acc);
        ov[j] = acc * dv;
    }
    float4* f4 = (float4*)(g_feat + (size_t)i * HID);
    #pragma unroll
    for (int q = 0; q < 4; q++) {
        float4 w = make_float4(ov[4*q], ov[4*q+1], ov[4*q+2], ov[4*q+3]);
        f4[q] = w;
        a4[q] = w;
    }
}

// Materialize final embeddings: h2 = dinv*agg2 + b2 (elementwise, coalesced).
__global__ void k_h2(const float* __restrict__ b2) {
    int t = blockIdx.x * blockDim.x + threadIdx.x;
    if (t < NN * HID) g_h2[t] = fmaf(g_dinv[t >> 4], g_agg[t], __ldg(&b2[t & 15]));
}

// Per original edge: sigmoid(h2[row] . h2[col]). 4 edges/thread, float4 out.
__global__ void k_score(const void* __restrict__ ei, float* __restrict__ out) {
    int t = blockIdx.x * blockDim.x + threadIdx.x;
    long long e = (long long)t * 4;
    if (e >= NE) return;
    int is64 = g_is64;
    int4 r4 = load_idx4(ei, e, is64);
    int4 c4 = load_idx4(ei, (long long)NE + e, is64);
    int rr[4] = {r4.x, r4.y, r4.z, r4.w};
    int cc[4] = {c4.x, c4.y, c4.z, c4.w};
    float s[4];
    #pragma unroll
    for (int k = 0; k < 4; k++) {
        const float4* hr = (const float4*)(g_h2 + (size_t)rr[k] * HID);
        const float4* hc = (const float4*)(g_h2 + (size_t)cc[k] * HID);
        float acc = 0.f;
        #pragma unroll
        for (int q = 0; q < 4; q++) {
            float4 a = hr[q], b = hc[q];
            acc += a.x * b.x + a.y * b.y + a.z * b.z + a.w * b.w;
        }
        s[k] = 1.0f / (1.0f + __expf(-acc));
    }
    *((float4*)(out + e)) = make_float4(s[0], s[1], s[2], s[3]);
}

extern "C" void kernel_launch(void* const* d_in, const int* in_sizes, int n_in,
                              void* d_out, int out_size) {
    const float* x  = nullptr;
    const void*  ei = nullptr;
    const float* W1 = nullptr;
    const float* b1 = nullptr;
    const float* W2 = nullptr;
    const float* b2 = nullptr;
    for (int i = 0; i < n_in; i++) {
        long long n = in_sizes[i];
        if      (n == (long long)NN * CIN)      x  = (const float*)d_in[i];
        else if (n == 2LL * NE)                 ei = d_in[i];
        else if (n == CIN * HID)                W1 = (const float*)d_in[i];
        else if (n == HID * HID)                W2 = (const float*)d_in[i];
        else if (n == HID) { if (!b1) b1 = (const float*)d_in[i]; else b2 = (const float*)d_in[i]; }
    }
    float* out = (float*)d_out;

    const int TB  = 256;
    const int gn  = (NN + TB - 1) / TB;
    const int ge4 = (NE / 4 + TB - 1) / TB;
    const int gw  = (NN * 32 + TB - 1) / TB;   // warp per node

    k_deg_init <<<gn,  TB>>>(ei);         // #1 (detect + zero)
    k_deg_count<<<ge4, TB>>>(ei);         // #2
    k_offsets  <<<gn,  TB>>>();           // #3
    k_fill     <<<ge4, TB>>>(ei);         // #4  <- profiler slot
    k_xform1   <<<NN/16, TB>>>(x, W1);    // #5
    k_pull     <<<gw,  TB>>>();           // #6
    k_layer2   <<<gn,  TB>>>(W2, b1);     // #7
    k_pull     <<<gw,  TB>>>();           // #8
    k_h2       <<<gn * HID, TB>>>(b2);    // #9
    k_score    <<<ge4, TB>>>(ei, out);    // #10
}

// round 9
// speedup vs baseline: 2.4682x; 1.0885x over previous
#include <cuda_runtime.h>

#define NN  100000
#define NE  3200000
#define CIN 128
#define HID 16

// Scratch (no allocations allowed): ~33 MB of __device__ globals.
__device__ int   g_degi[NN];          // in-degree (excl. self)
__device__ float g_dinv[NN];          // rsqrt(1+deg)
__device__ int   g_off[NN];           // CSR segment start
__device__ int   g_cur[NN];           // fill cursor
__device__ int   g_nbr[NE];           // CSR: source node per incoming edge
__device__ int   g_total;             // segment allocator
__device__ float g_feat[NN * HID];    // pre-scaled features fed to edge gather
__device__ float g_agg[NN * HID];     // aggregation target (init = self-loop term)
__device__ float g_h2[NN * HID];      // final embeddings
__device__ int   g_is64;              // 1 if edge_index is int64, 0 if int32

__device__ __forceinline__ int clampi(long long v) {
    v = v < 0 ? 0 : (v >= NN ? NN - 1 : v);
    return (int)v;
}

// Load 4 consecutive indices starting at element pos (pos % 4 == 0).
__device__ __forceinline__ int4 load_idx4(const void* ei, long long pos, int is64) {
    if (!is64) {
        int4 t = __ldg((const int4*)((const int*)ei + pos));
        return make_int4(clampi(t.x), clampi(t.y), clampi(t.z), clampi(t.w));
    } else {
        longlong2 a = __ldg((const longlong2*)((const long long*)ei + pos));
        longlong2 b = __ldg((const longlong2*)((const long long*)ei + pos + 2));
        return make_int4(clampi(a.x), clampi(a.y), clampi(b.x), clampi(b.y));
    }
}

// Single index load (broadcast-friendly).
__device__ __forceinline__ int load_idx1(const void* ei, long long pos, int is64) {
    long long v = is64 ? __ldg((const long long*)ei + pos)
                       : (long long)__ldg((const int*)ei + pos);
    return clampi(v);
}

// zero counters + (block 0) index-dtype detection, fused.
__global__ void k_deg_init(const void* ei) {
    if (blockIdx.x == 0) {
        __shared__ int bad;
        if (threadIdx.x == 0) { bad = 0; g_total = 0; }
        __syncthreads();
        long long pos = (long long)threadIdx.x * (NE / 256);
        long long v = ((const long long*)ei)[pos];
        if (v < 0 || v >= NN) atomicOr(&bad, 1);
        __syncthreads();
        if (threadIdx.x == 0) g_is64 = bad ? 0 : 1;
    }
    int i = blockIdx.x * blockDim.x + threadIdx.x;
    if (i < NN) g_degi[i] = 0;
}

__global__ void k_deg_count(const void* __restrict__ ei) {
    int t = blockIdx.x * blockDim.x + threadIdx.x;
    long long e = (long long)t * 4;
    if (e >= NE) return;
    int4 c = load_idx4(ei, (long long)NE + e, g_is64);   // col half
    atomicAdd(&g_degi[c.x], 1);
    atomicAdd(&g_degi[c.y], 1);
    atomicAdd(&g_degi[c.z], 1);
    atomicAdd(&g_degi[c.w], 1);
}

// Per-block exclusive scan + global segment allocation; also dinv = rsqrt(1+deg).
__global__ void k_offsets() {
    __shared__ int s[256];
    __shared__ int base;
    int i = blockIdx.x * 256 + threadIdx.x;
    int d = (i < NN) ? g_degi[i] : 0;
    s[threadIdx.x] = d;
    __syncthreads();
    #pragma unroll
    for (int ofs = 1; ofs < 256; ofs <<= 1) {
        int v = (threadIdx.x >= ofs) ? s[threadIdx.x - ofs] : 0;
        __syncthreads();
        s[threadIdx.x] += v;
        __syncthreads();
    }
    if (threadIdx.x == 255) base = atomicAdd(&g_total, s[255]);
    __syncthreads();
    if (i < NN) {
        int excl = base + s[threadIdx.x] - d;
        g_off[i] = excl;
        g_cur[i] = excl;
        g_dinv[i] = rsqrtf(1.0f + (float)d);
    }
}

// CSR fill: nbr[cursor[col]++] = row. Order within a segment is arbitrary.
__global__ void k_fill(const void* __restrict__ ei) {
    int t = blockIdx.x * blockDim.x + threadIdx.x;
    long long e = (long long)t * 4;
    if (e >= NE) return;
    int is64 = g_is64;
    int4 r4 = load_idx4(ei, e, is64);
    int4 c4 = load_idx4(ei, (long long)NE + e, is64);
    int rr[4] = {r4.x, r4.y, r4.z, r4.w};
    int cc[4] = {c4.x, c4.y, c4.z, c4.w};
    #pragma unroll
    for (int k = 0; k < 4; k++) {
        int pos = atomicAdd(&g_cur[cc[k]], 1);
        g_nbr[pos] = rr[k];
    }
}

// Layer-1 transform with shared staging: 16 nodes/block.
#define XS_STR 132   // padded row stride (floats)
__global__ void k_xform1(const float* __restrict__ x, const float* __restrict__ W1) {
    __shared__ float sX[16 * XS_STR];
    __shared__ float sWt[HID * XS_STR];
    const float* xb = x + (size_t)blockIdx.x * 16 * CIN;
    #pragma unroll
    for (int L = threadIdx.x; L < 16 * CIN; L += 256) {
        int n = L >> 7, k = L & 127;
        sX[n * XS_STR + k] = xb[L];
    }
    #pragma unroll
    for (int L = threadIdx.x; L < CIN * HID; L += 256) {
        int k = L >> 4, j = L & 15;
        sWt[j * XS_STR + k] = W1[L];
    }
    __syncthreads();
    int nloc = threadIdx.x >> 4;
    int j    = threadIdx.x & 15;
    int node = blockIdx.x * 16 + nloc;
    const float4* xr = (const float4*)(sX  + nloc * XS_STR);
    const float4* wr = (const float4*)(sWt + j    * XS_STR);
    float acc = 0.f;
    #pragma unroll
    for (int k4 = 0; k4 < CIN / 4; k4++) {
        float4 xv = xr[k4];
        float4 wv = wr[k4];
        acc = fmaf(xv.x, wv.x, acc);
        acc = fmaf(xv.y, wv.y, acc);
        acc = fmaf(xv.z, wv.z, acc);
        acc = fmaf(xv.w, wv.w, acc);
    }
    float v = acc * g_dinv[node];
    int tid = blockIdx.x * 256 + threadIdx.x;
    g_feat[tid] = v;
    g_agg[tid]  = v;
}

// Pull aggregation: one warp per node. FUSE==0: agg += sum. FUSE==1: h2 = dinv*(agg+sum)+b2.
template <int FUSE>
__global__ void k_pull(const float* __restrict__ b2) {
    int warp = (blockIdx.x * blockDim.x + threadIdx.x) >> 5;
    if (warp >= NN) return;
    int lane = threadIdx.x & 31;
    int j    = lane & 15;
    int half = lane >> 4;             // 0 or 1
    int start = g_off[warp];
    int deg   = g_degi[warp];
    float acc = 0.f;
    for (int base = 0; base < deg; base += 32) {
        int myn = (base + lane < deg) ? g_nbr[start + base + lane] : 0;
        int lim = min(32, deg - base);
        #pragma unroll 4
        for (int k = 0; k < 32; k += 2) {
            if (k >= lim) break;
            int r = __shfl_sync(0xffffffffu, myn, k + half);
            if (k + half < lim)
                acc += g_feat[(size_t)r * HID + j];
        }
    }
    acc += __shfl_xor_sync(0xffffffffu, acc, 16);
    if (lane < 16) {
        size_t idx = (size_t)warp * HID + j;
        if (FUSE == 0) {
            g_agg[idx] += acc;
        } else {
            g_h2[idx] = fmaf(g_dinv[warp], g_agg[idx] + acc, __ldg(&b2[j]));
        }
    }
}

// Layer-2: h1 = relu(dinv*agg1 + b1); g2 = (h1 @ W2) * dinv; agg2 init = g2.
__global__ void k_layer2(const float* __restrict__ W2, const float* __restrict__ b1) {
    __shared__ float sW[HID * HID];
    __shared__ float sb[HID];
    if (threadIdx.x < HID * HID) sW[threadIdx.x] = W2[threadIdx.x];
    if (threadIdx.x < HID)       sb[threadIdx.x] = b1[threadIdx.x];
    __syncthreads();
    int i = blockIdx.x * blockDim.x + threadIdx.x;
    if (i >= NN) return;
    float dv = g_dinv[i];
    float4* a4 = (float4*)(g_agg + (size_t)i * HID);
    float h[HID];
    #pragma unroll
    for (int q = 0; q < 4; q++) {
        float4 A = a4[q];
        h[4*q + 0] = fmaxf(fmaf(dv, A.x, sb[4*q + 0]), 0.f);
        h[4*q + 1] = fmaxf(fmaf(dv, A.y, sb[4*q + 1]), 0.f);
        h[4*q + 2] = fmaxf(fmaf(dv, A.z, sb[4*q + 2]), 0.f);
        h[4*q + 3] = fmaxf(fmaf(dv, A.w, sb[4*q + 3]), 0.f);
    }
    float ov[HID];
    #pragma unroll
    for (int j = 0; j < HID; j++) {
        float acc = 0.f;
        #pragma unroll
        for (int k = 0; k < HID; k++) acc = fmaf(h[k], sW[k * HID + j], acc);
        ov[j] = acc * dv;
    }
    float4* f4 = (float4*)(g_feat + (size_t)i * HID);
    #pragma unroll
    for (int q = 0; q < 4; q++) {
        float4 w = make_float4(ov[4*q], ov[4*q+1], ov[4*q+2], ov[4*q+3]);
        f4[q] = w;
        a4[q] = w;
    }
}

// Score: 4 lanes cooperate per edge (lane group loads 4 consecutive float4s
// of each row -> 2 sectors/row instead of 4 independent wavefronts).
__global__ void k_score(const void* __restrict__ ei, float* __restrict__ out) {
    int t = blockIdx.x * blockDim.x + threadIdx.x;   // lane-groups of 4
    long long e = t >> 2;                            // edge id
    if (e >= NE) return;
    int q = t & 3;                                   // quadrant 0..3
    int is64 = g_is64;
    int r = load_idx1(ei, e, is64);                  // 4 lanes same addr -> broadcast
    int c = load_idx1(ei, (long long)NE + e, is64);
    float4 a = __ldg((const float4*)(g_h2 + (size_t)r * HID) + q);
    float4 b = __ldg((const float4*)(g_h2 + (size_t)c * HID) + q);
    float s = a.x * b.x + a.y * b.y + a.z * b.z + a.w * b.w;
    s += __shfl_xor_sync(0xffffffffu, s, 1);
    s += __shfl_xor_sync(0xffffffffu, s, 2);
    if (q == 0) out[e] = 1.0f / (1.0f + __expf(-s));
}

extern "C" void kernel_launch(void* const* d_in, const int* in_sizes, int n_in,
                              void* d_out, int out_size) {
    const float* x  = nullptr;
    const void*  ei = nullptr;
    const float* W1 = nullptr;
    const float* b1 = nullptr;
    const float* W2 = nullptr;
    const float* b2 = nullptr;
    for (int i = 0; i < n_in; i++) {
        long long n = in_sizes[i];
        if      (n == (long long)NN * CIN)      x  = (const float*)d_in[i];
        else if (n == 2LL * NE)                 ei = d_in[i];
        else if (n == CIN * HID)                W1 = (const float*)d_in[i];
        else if (n == HID * HID)                W2 = (const float*)d_in[i];
        else if (n == HID) { if (!b1) b1 = (const float*)d_in[i]; else b2 = (const float*)d_in[i]; }
    }
    float* out = (float*)d_out;

    const int TB  = 256;
    const int gn  = (NN + TB - 1) / TB;
    const int ge4 = (NE / 4 + TB - 1) / TB;
    const int gw  = (NN * 32 + TB - 1) / TB;        // warp per node
    const int gs  = ((long long)NE * 4 + TB - 1) / TB;  // 4 lanes per edge

    k_deg_init   <<<gn,  TB>>>(ei);        // #1 (detect + zero)
    k_deg_count  <<<ge4, TB>>>(ei);        // #2
    k_offsets    <<<gn,  TB>>>();          // #3
    k_fill       <<<ge4, TB>>>(ei);        // #4  <- profiler slot
    k_xform1     <<<NN/16, TB>>>(x, W1);   // #5
    k_pull<0>    <<<gw,  TB>>>(nullptr);   // #6
    k_layer2     <<<gn,  TB>>>(W2, b1);    // #7
    k_pull<1>    <<<gw,  TB>>>(b2);        // #8 (fused h2)
    k_score      <<<gs,  TB>>>(ei, out);   // #9
}